// round 6
// baseline (speedup 1.0000x reference)
#include <cuda_runtime.h>

#define B_TOT   16
#define CIN     64
#define COUT    64
#define S_LEN   1024
#define KW      3
#define STILE   32
#define POSN    (STILE + 2)     // 34 input positions per tile (halo of 1 each side)
#define BH      8               // batches per block
#define OTILE   2               // outputs per thread  (was 4 -> halves reg pressure)
#define OGN     8               // warps per block
#define OBLK    (OGN * OTILE)   // 16 outputs per block
#define NTHREADS 256
#define SMEM_FLOATS (CIN * BH * POSN)   // 64*8*34 = 17408 floats = 69632 B

__global__ void __launch_bounds__(NTHREADS, 3)
locon1d_kernel(const float* __restrict__ X,     // (B, Cin, S)
               const float* __restrict__ W,     // (Cout, Cin, S, K)
               const float* __restrict__ Bias,  // (Cout, S)
               float* __restrict__ Out)         // (B, Cout, S)
{
    extern __shared__ float shx[];   // layout: [c][b][pos] -> (c*BH + b)*POSN + pos

    const int s0     = blockIdx.x * STILE;
    const int o0base = blockIdx.y * OBLK;
    const int b0     = blockIdx.z * BH;
    const int tid    = threadIdx.x;
    const int sl     = tid & 31;     // lane = consecutive s
    const int wid    = tid >> 5;     // warp id

    // ── Input tile fill: warp = batch, lane = position. Coalesced 128B rows,
    //    no div/mod in the hot path (b fixed per warp, c is the loop var).
    {
        const float* xb  = X + ((size_t)(b0 + wid) * CIN) * S_LEN;
        float*       shb = shx + (size_t)wid * POSN;
        const int sg  = s0 - 1 + sl;        // main 32 positions
        const int sg2 = s0 + 31 + sl;       // tail positions 32,33 (lanes 0,1)
        const bool m1 = (unsigned)sg  < (unsigned)S_LEN;
        const bool m2 = (sl < 2) && ((unsigned)sg2 < (unsigned)S_LEN);
        #pragma unroll 4
        for (int c = 0; c < CIN; c++) {
            float v = m1 ? xb[(size_t)c * S_LEN + sg] : 0.0f;
            shb[(size_t)c * (BH * POSN) + sl] = v;
            if (sl < 2) {
                float u = m2 ? xb[(size_t)c * S_LEN + sg2] : 0.0f;
                shb[(size_t)c * (BH * POSN) + 32 + sl] = u;
            }
        }
    }
    __syncthreads();

    const int s  = s0 + sl;
    const int o0 = o0base + wid * OTILE;

    // acc[j][b]: 2 outputs x 8 batches = 16 registers.
    float acc[OTILE][BH];
    #pragma unroll
    for (int j = 0; j < OTILE; j++) {
        float bv = Bias[(size_t)(o0 + j) * S_LEN + s];
        #pragma unroll
        for (int b = 0; b < BH; b++) acc[j][b] = bv;
    }

    // Weight pointers for the two o's this thread owns (lanes = consecutive s
    // -> each warp-LDG covers 384B contiguous).
    const float* wp0 = W + ((size_t)o0 * CIN) * (S_LEN * KW) + (size_t)s * KW;
    const float* wp1 = wp0 + (size_t)CIN * S_LEN * KW;

    #pragma unroll 4
    for (int c = 0; c < CIN; c++) {
        const float* wc0 = wp0 + (size_t)c * (S_LEN * KW);
        const float* wc1 = wp1 + (size_t)c * (S_LEN * KW);
        const float wA0 = wc0[0], wA1 = wc0[1], wA2 = wc0[2];
        const float wB0 = wc1[0], wB1 = wc1[1], wB2 = wc1[2];

        const float* xc = shx + (size_t)c * (BH * POSN) + sl;
        #pragma unroll
        for (int b = 0; b < BH; b++) {
            const float x0 = xc[b * POSN + 0];
            const float x1 = xc[b * POSN + 1];
            const float x2 = xc[b * POSN + 2];
            acc[0][b] += wA0 * x0;
            acc[0][b] += wA1 * x1;
            acc[0][b] += wA2 * x2;
            acc[1][b] += wB0 * x0;
            acc[1][b] += wB1 * x1;
            acc[1][b] += wB2 * x2;
        }
    }

    // Store: lanes = consecutive s -> fully coalesced 128B stores per warp.
    #pragma unroll
    for (int j = 0; j < OTILE; j++) {
        #pragma unroll
        for (int b = 0; b < BH; b++) {
            Out[((size_t)(b0 + b) * COUT + (o0 + j)) * S_LEN + s] = acc[j][b];
        }
    }
}

extern "C" void kernel_launch(void* const* d_in, const int* in_sizes, int n_in,
                              void* d_out, int out_size) {
    const float* x    = (const float*)d_in[0];
    const float* w    = (const float*)d_in[1];
    const float* bias = (const float*)d_in[2];
    float* out        = (float*)d_out;

    const int smem_bytes = SMEM_FLOATS * (int)sizeof(float);  // 69632 B > 48K -> opt-in
    cudaFuncSetAttribute(locon1d_kernel,
                         cudaFuncAttributeMaxDynamicSharedMemorySize, smem_bytes);

    // (32, 4, 2) = 256 blocks -> covers all 148 SMs, ~2 blocks (16 warps)/SM.
    dim3 grid(S_LEN / STILE, COUT / OBLK, B_TOT / BH);
    locon1d_kernel<<<grid, NTHREADS, smem_bytes>>>(x, w, bias, out);
}

// round 10
// speedup vs baseline: 2.0793x; 2.0793x over previous
#include <cuda_runtime.h>

#define B_TOT   16
#define CIN     64
#define COUT    64
#define S_LEN   1024
#define KW      3
#define STILE   32
#define POSN    (STILE + 2)     // 34 input positions per tile (halo of 1 each side)
#define BH      8               // batches per block
#define OTILE   4               // outputs per thread (R4 value — protects ILP)
#define OGN     8               // o-groups per c-half
#define OBLK    (OGN * OTILE)   // 32 outputs per block
#define CHALF   (CIN / 2)       // 32 c per warp-half
#define NTHREADS 512            // 16 warps: [c-half][o-group]
#define SMEM_FLOATS (CIN * BH * POSN)   // 64*8*34 = 17408 floats = 69632 B
// epilogue reuses shx as a 256-thread x 32-float buffer (8192 floats <= SMEM_FLOATS)

__global__ void __launch_bounds__(NTHREADS, 1)
locon1d_kernel(const float* __restrict__ X,     // (B, Cin, S)
               const float* __restrict__ W,     // (Cout, Cin, S, K)
               const float* __restrict__ Bias,  // (Cout, S)
               float* __restrict__ Out)         // (B, Cout, S)
{
    extern __shared__ float shx[];   // [c][b][pos] -> (c*BH + b)*POSN + pos

    const int s0     = blockIdx.x * STILE;
    const int o0base = blockIdx.y * OBLK;
    const int b0     = blockIdx.z * BH;
    const int tid    = threadIdx.x;
    const int sl     = tid & 31;          // lane = consecutive s
    const int wid    = tid >> 5;          // 0..15
    const int og     = wid & 7;           // o-group
    const int ch     = wid >> 3;          // c-half: 0 or 1

    // ── Cooperative input tile fill (512 threads, coalesced along pos).
    for (int i = tid; i < SMEM_FLOATS; i += NTHREADS) {
        int pos = i % POSN;
        int bc  = i / POSN;
        int b   = bc % BH;
        int c   = bc / BH;
        int sg  = s0 - 1 + pos;
        float v = 0.0f;
        if ((unsigned)sg < (unsigned)S_LEN)
            v = X[((size_t)(b0 + b) * CIN + c) * S_LEN + sg];
        shx[i] = v;
    }
    __syncthreads();

    const int s  = s0 + sl;
    const int o0 = o0base + og * OTILE;

    // acc[j][b]: 4 outputs x 8 batches = 32 registers.
    // c-half 0 starts from bias; c-half 1 starts from zero (partial sum).
    float acc[OTILE][BH];
    #pragma unroll
    for (int j = 0; j < OTILE; j++) {
        float bv = (ch == 0) ? Bias[(size_t)(o0 + j) * S_LEN + s] : 0.0f;
        #pragma unroll
        for (int b = 0; b < BH; b++) acc[j][b] = bv;
    }

    // Weight base for (o0, c = ch*CHALF, s, k=0).
    const float* wbase = W + (size_t)o0 * (CIN * S_LEN * KW)
                           + (size_t)(ch * CHALF) * (S_LEN * KW)
                           + (size_t)s * KW;
    const float* xhalf = shx + (size_t)(ch * CHALF) * (BH * POSN) + sl;

    #pragma unroll 2
    for (int ci = 0; ci < CHALF; ci++) {
        // x window: 8 batches x 3 taps from shared (conflict-free: lanes are the
        // fastest smem dimension).
        float xr[BH][KW];
        const float* xc = xhalf + (size_t)ci * (BH * POSN);
        #pragma unroll
        for (int b = 0; b < BH; b++) {
            #pragma unroll
            for (int k = 0; k < KW; k++)
                xr[b][k] = xc[b * POSN + k];
        }

        const float* wc = wbase + (size_t)ci * (S_LEN * KW);
        #pragma unroll
        for (int j = 0; j < OTILE; j++) {
            const float* wj = wc + (size_t)j * (CIN * S_LEN * KW);
            float w0 = wj[0];
            float w1 = wj[1];
            float w2 = wj[2];
            #pragma unroll
            for (int b = 0; b < BH; b++) {
                acc[j][b] += w0 * xr[b][0];
                acc[j][b] += w1 * xr[b][1];
                acc[j][b] += w2 * xr[b][2];
            }
        }
    }

    // ── Cross-half reduction through smem (reuse shx; x tile is dead now).
    __syncthreads();                       // all mainloop reads of shx done
    const int t2 = og * 32 + sl;           // 0..255 thread id within a half
    if (ch == 1) {
        // buf[(j*BH+b)*256 + t2]: for fixed (j,b) lanes hit consecutive floats
        // -> conflict-free STS/LDS.
        #pragma unroll
        for (int j = 0; j < OTILE; j++)
            #pragma unroll
            for (int b = 0; b < BH; b++)
                shx[(j * BH + b) * 256 + t2] = acc[j][b];
    }
    __syncthreads();
    if (ch == 0) {
        #pragma unroll
        for (int j = 0; j < OTILE; j++) {
            #pragma unroll
            for (int b = 0; b < BH; b++) {
                float v = acc[j][b] + shx[(j * BH + b) * 256 + t2];
                // lanes = consecutive s -> fully coalesced 128B stores per warp.
                Out[((size_t)(b0 + b) * COUT + (o0 + j)) * S_LEN + s] = v;
            }
        }
    }
}

extern "C" void kernel_launch(void* const* d_in, const int* in_sizes, int n_in,
                              void* d_out, int out_size) {
    const float* x    = (const float*)d_in[0];
    const float* w    = (const float*)d_in[1];
    const float* bias = (const float*)d_in[2];
    float* out        = (float*)d_out;

    const int smem_bytes = SMEM_FLOATS * (int)sizeof(float);  // 69632 B > 48K -> opt-in
    cudaFuncSetAttribute(locon1d_kernel,
                         cudaFuncAttributeMaxDynamicSharedMemorySize, smem_bytes);

    dim3 grid(S_LEN / STILE, COUT / OBLK, B_TOT / BH);  // (32, 2, 2) = 128 blocks
    locon1d_kernel<<<grid, NTHREADS, smem_bytes>>>(x, w, bias, out);
}